// round 10
// baseline (speedup 1.0000x reference)
#include <cuda_runtime.h>
#include <math.h>

#define B_ 1024
#define V_ 50000
#define H_ 100
#define K_ 200
#define T_ 32768
#define BN_EPS 1e-5f

// GEMM1 config: split-K over V
#define S1  50        // splits
#define VC  1000      // V-chunk per split
#define KB1 20        // k-tile
#define BM1 64        // rows per block

// GEMM2 config
#define KB2 8

// final pass: column chunks of 512
#define NC 98

// ---------------- scratch (__device__ globals; no allocation) ----------------
__device__ float g_p1[S1 * B_ * H_];          // gemm1 split partials (20.5MB)
__device__ float g_h1[B_ * H_];
__device__ float g_h2[B_ * H_];
__device__ float g_mulin[B_ * K_];
__device__ float g_siglin[B_ * K_];
__device__ float g_kA[2 * K_];                // BN affine A for mu (0..199), sig (200..399)
__device__ float g_kC[2 * K_];
__device__ float g_theta[B_ * K_];
__device__ float g_X[(size_t)B_ * V_];        // 204.8MB logits (pre-BN)
__device__ float g_av[V_];
__device__ float g_cv[V_];
__device__ int   g_cnt[V_];
__device__ float g_ep[B_ * NC];
__device__ float g_wp[B_ * NC];

typedef unsigned long long ull;

// packed dual-FMA: bit-identical to two independent fma.rn.f32
__device__ __forceinline__ ull ffma2(ull a, ull b, ull c) {
    ull d;
    asm("fma.rn.f32x2 %0, %1, %2, %3;" : "=l"(d) : "l"(a), "l"(b), "l"(c));
    return d;
}
__device__ __forceinline__ float2 unpack2(ull v) {
    float2 f;
    asm("mov.b64 {%0, %1}, %2;" : "=f"(f.x), "=f"(f.y) : "l"(v));
    return f;
}

__device__ __forceinline__ float softplusf(float x) {
    // stable: matches jax.nn.softplus = logaddexp(x, 0)
    return fmaxf(x, 0.0f) + log1pf(expf(-fabsf(x)));
}

// FMA-pipe exp: valid for |y| < ~80 (here |y| <= ~40). rel err ~5e-8.
__device__ __forceinline__ float exp_fast(float y) {
    const float LOG2E = 1.4426950408889634f;
    const float MAGIC = 12582912.0f;      // 1.5 * 2^23
    float t = y * LOG2E;
    float z = t + MAGIC;
    int   n = __float_as_int(z) - 0x4B400000;
    float f = t - (z - MAGIC);            // |f| <= 0.5 (+eps)
    float p = 1.5252733e-5f;
    p = fmaf(p, f, 1.5403531e-4f);
    p = fmaf(p, f, 1.3333558e-3f);
    p = fmaf(p, f, 9.6181291e-3f);
    p = fmaf(p, f, 5.5504109e-2f);
    p = fmaf(p, f, 2.4022651e-1f);
    p = fmaf(p, f, 6.9314718e-1f);
    p = fmaf(p, f, 1.0f);
    return p * __int_as_float((n + 127) << 23);
}

// =====================================================================
// GEMM1: split-K partials of bows[B,V] @ fc1_w[V,H]
// Double-buffered software pipeline: global->reg prefetch overlaps compute.
// grid (S1, B/BM1), 224 threads (200 compute: 8x25), thread tile 8x4 FFMA2.
// =====================================================================
__global__ __launch_bounds__(224) void k_gemm1(const float* __restrict__ bows,
                                               const float* __restrict__ w) {
    __shared__ __align__(16) float2 As2[2][BM1 * KB1];  // dup pairs, 2x10.2KB
    __shared__ __align__(16) float  Ws[2][KB1 * H_];    // 2x8KB
    const int s   = blockIdx.x;
    const int rb  = blockIdx.y;
    const int tid = threadIdx.x;
    const int rw  = tid / 25;
    const int cw  = tid % 25;

    ull acc[8][2];
#pragma unroll
    for (int i = 0; i < 8; i++) { acc[i][0] = 0ull; acc[i][1] = 0ull; }

    const int vb = s * VC;
    // fill tile 0
    for (int idx = tid; idx < BM1 * (KB1 / 2); idx += 224) {
        int m = idx / (KB1 / 2), kp = idx % (KB1 / 2);
        float2 a = *(const float2*)&bows[(size_t)(rb * BM1 + m) * V_ + vb + 2 * kp];
        As2[0][m * KB1 + 2 * kp]     = make_float2(a.x, a.x);
        As2[0][m * KB1 + 2 * kp + 1] = make_float2(a.y, a.y);
    }
    for (int idx = tid; idx < KB1 * (H_ / 2); idx += 224) {
        int kk = idx / (H_ / 2), h2 = idx % (H_ / 2);
        *(float2*)&Ws[0][kk * H_ + 2 * h2] =
            *(const float2*)&w[(size_t)(vb + kk) * H_ + 2 * h2];
    }
    __syncthreads();

    const int NIT = VC / KB1;   // 50
    for (int it = 0; it < NIT; ++it) {
        const int cur = it & 1, nxt = cur ^ 1;
        const bool has = (it + 1 < NIT);
        const int v0n = vb + (it + 1) * KB1;
        // prefetch next tile into registers (latency overlaps compute below)
        float2 a_pf[3], w_pf[5];
        if (has) {
#pragma unroll
            for (int r = 0; r < 3; r++) {
                int idx = tid + r * 224;
                if (idx < BM1 * (KB1 / 2)) {
                    int m = idx / (KB1 / 2), kp = idx % (KB1 / 2);
                    a_pf[r] = *(const float2*)&bows[(size_t)(rb * BM1 + m) * V_ + v0n + 2 * kp];
                }
            }
#pragma unroll
            for (int r = 0; r < 5; r++) {
                int idx = tid + r * 224;
                if (idx < KB1 * (H_ / 2)) {
                    int kk = idx / (H_ / 2), h2 = idx % (H_ / 2);
                    w_pf[r] = *(const float2*)&w[(size_t)(v0n + kk) * H_ + 2 * h2];
                }
            }
        }
        // compute on current tile
        if (tid < 200) {
#pragma unroll
            for (int kp = 0; kp < KB1; kp += 2) {
                ulonglong2 ap[8];
#pragma unroll
                for (int i = 0; i < 8; i++)
                    ap[i] = *(const ulonglong2*)&As2[cur][(rw * 8 + i) * KB1 + kp];
                ulonglong2 wv0 = *(const ulonglong2*)&Ws[cur][kp * H_ + cw * 4];
                ulonglong2 wv1 = *(const ulonglong2*)&Ws[cur][(kp + 1) * H_ + cw * 4];
#pragma unroll
                for (int i = 0; i < 8; i++) {
                    acc[i][0] = ffma2(ap[i].x, wv0.x, acc[i][0]);
                    acc[i][1] = ffma2(ap[i].x, wv0.y, acc[i][1]);
                    acc[i][0] = ffma2(ap[i].y, wv1.x, acc[i][0]);
                    acc[i][1] = ffma2(ap[i].y, wv1.y, acc[i][1]);
                }
            }
        }
        // commit prefetch to the other buffer
        if (has) {
#pragma unroll
            for (int r = 0; r < 3; r++) {
                int idx = tid + r * 224;
                if (idx < BM1 * (KB1 / 2)) {
                    int m = idx / (KB1 / 2), kp = idx % (KB1 / 2);
                    As2[nxt][m * KB1 + 2 * kp]     = make_float2(a_pf[r].x, a_pf[r].x);
                    As2[nxt][m * KB1 + 2 * kp + 1] = make_float2(a_pf[r].y, a_pf[r].y);
                }
            }
#pragma unroll
            for (int r = 0; r < 5; r++) {
                int idx = tid + r * 224;
                if (idx < KB1 * (H_ / 2)) {
                    int kk = idx / (H_ / 2), h2 = idx % (H_ / 2);
                    *(float2*)&Ws[nxt][kk * H_ + 2 * h2] = w_pf[r];
                }
            }
        }
        __syncthreads();
    }
    if (tid < 200) {
        float* out = g_p1 + (size_t)s * (B_ * H_);
#pragma unroll
        for (int i = 0; i < 8; i++) {
            int row = rb * BM1 + rw * 8 + i;
#pragma unroll
            for (int j = 0; j < 2; j++) {
                float2 r = unpack2(acc[i][j]);
                out[row * H_ + cw * 4 + 2 * j]     = r.x;
                out[row * H_ + cw * 4 + 2 * j + 1] = r.y;
            }
        }
    }
}

// reduce split partials + bias + softplus -> g_h1
__global__ void k_red1(const float* __restrict__ b1) {
    int i = blockIdx.x * blockDim.x + threadIdx.x;
    if (i >= B_ * H_) return;
    float s = 0.f;
    for (int t = 0; t < S1; t++) s += g_p1[(size_t)t * (B_ * H_) + i];
    s += b1[i % H_];
    g_h1[i] = softplusf(s);
}

// h2 = softplus(h1 @ fc2_w + b)
__global__ void k_h2(const float* __restrict__ w2, const float* __restrict__ b2) {
    int i = blockIdx.x * blockDim.x + threadIdx.x;
    if (i >= B_ * H_) return;
    int b = i / H_, h = i % H_;
    const float* hr = g_h1 + b * H_;
    float s = b2[h];
    for (int j = 0; j < H_; j++) s = fmaf(hr[j], w2[j * H_ + h], s);
    g_h2[i] = softplusf(s);
}

// mu_lin / sig_lin = h2 @ {mu_w, sig_w} + bias
__global__ void k_musig(const float* __restrict__ muw, const float* __restrict__ mub,
                        const float* __restrict__ sgw, const float* __restrict__ sgb) {
    int i = blockIdx.x * blockDim.x + threadIdx.x;
    if (i >= 2 * B_ * K_) return;
    int which = i / (B_ * K_);
    int r = i % (B_ * K_);
    int b = r / K_, k = r % K_;
    const float* hr = g_h2 + b * H_;
    const float* w  = which ? sgw : muw;
    float s = which ? sgb[k] : mub[k];
    for (int j = 0; j < H_; j++) s = fmaf(hr[j], w[j * K_ + k], s);
    (which ? g_siglin : g_mulin)[b * K_ + k] = s;
}

// BN stats over batch for mu_lin (cols 0..199) and sig_lin (cols 200..399)
__global__ __launch_bounds__(256) void k_bnk(const float* __restrict__ mug, const float* __restrict__ mubb,
                                             const float* __restrict__ sgg, const float* __restrict__ sgbb) {
    __shared__ float ssum[256], ssq[256];
    int col = blockIdx.x;                 // 0..399
    int c = (col < K_) ? col : col - K_;
    const float* x = (col < K_) ? g_mulin : g_siglin;
    float x0 = x[c];                      // row-0 shift
    float s = 0.f, q = 0.f;
    for (int b = threadIdx.x; b < B_; b += 256) {
        float d = x[b * K_ + c] - x0;
        s += d; q += d * d;
    }
    ssum[threadIdx.x] = s; ssq[threadIdx.x] = q;
    __syncthreads();
    for (int o = 128; o > 0; o >>= 1) {
        if (threadIdx.x < o) {
            ssum[threadIdx.x] += ssum[threadIdx.x + o];
            ssq[threadIdx.x]  += ssq[threadIdx.x + o];
        }
        __syncthreads();
    }
    if (threadIdx.x == 0) {
        float mean_d = ssum[0] * (1.f / B_);
        float var    = ssq[0] * (1.f / B_) - mean_d * mean_d;
        float mean   = x0 + mean_d;
        float g  = (col < K_) ? mug[c]  : sgg[c];
        float bb = (col < K_) ? mubb[c] : sgbb[c];
        float a  = g * rsqrtf(var + BN_EPS);
        g_kA[col] = a;
        g_kC[col] = bb - a * mean;
    }
}

// theta = exp(bn(mu) + exp(0.5*bn(sig)) * eps)
__global__ void k_theta(const float* __restrict__ eps) {
    int i = blockIdx.x * blockDim.x + threadIdx.x;
    if (i >= B_ * K_) return;
    int k = i % K_;
    float m  = fmaf(g_kA[k], g_mulin[i], g_kC[k]);
    float sg = expf(0.5f * fmaf(g_kA[K_ + k], g_siglin[i], g_kC[K_ + k]));
    g_theta[i] = expf(fmaf(sg, eps[i], m));
}

// =====================================================================
// GEMM2: X[B,V] = theta[B,K] @ beta_w[K,V] + beta_b
// Double-buffered software pipeline; 256 thr, 8x8 thread tile via FFMA2;
// vectorized float4 epilogue on full tiles.
// =====================================================================
__global__ __launch_bounds__(256) void k_gemm2(const float* __restrict__ bw,
                                               const float* __restrict__ bb) {
    __shared__ __align__(16) float2 As2[2][128 * KB2]; // dup pairs, 2x8KB
    __shared__ __align__(16) float  Ws[2][KB2 * 128];  // 2x4KB
    const int cb  = blockIdx.x;
    const int rb  = blockIdx.y;
    const int tid = threadIdx.x;
    const int tx  = tid % 16;
    const int ty  = tid / 16;
    const int vbase = cb * 128;

    ull acc[8][4];
#pragma unroll
    for (int i = 0; i < 8; i++)
#pragma unroll
        for (int j = 0; j < 4; j++) acc[i][j] = 0ull;

    // fill tile 0
    for (int idx = tid; idx < 128 * (KB2 / 2); idx += 256) {
        int m = idx / (KB2 / 2), kp = idx % (KB2 / 2);
        float2 a = *(const float2*)&g_theta[(rb * 128 + m) * K_ + 2 * kp];
        As2[0][m * KB2 + 2 * kp]     = make_float2(a.x, a.x);
        As2[0][m * KB2 + 2 * kp + 1] = make_float2(a.y, a.y);
    }
    {
        int kk = tid / 32, c4 = tid % 32;
        int v = vbase + c4 * 4;
        float4 val;
        if (v + 3 < V_) val = *(const float4*)&bw[(size_t)kk * V_ + v];
        else {
            val.x = (v     < V_) ? bw[(size_t)kk * V_ + v]     : 0.f;
            val.y = (v + 1 < V_) ? bw[(size_t)kk * V_ + v + 1] : 0.f;
            val.z = (v + 2 < V_) ? bw[(size_t)kk * V_ + v + 2] : 0.f;
            val.w = 0.f;
        }
        *(float4*)&Ws[0][kk * 128 + c4 * 4] = val;
    }
    __syncthreads();

    const int NIT = K_ / KB2;   // 25
    for (int it = 0; it < NIT; ++it) {
        const int cur = it & 1, nxt = cur ^ 1;
        const bool has = (it + 1 < NIT);
        const int k0n = (it + 1) * KB2;
        // prefetch next tile into registers
        float2 a_pf[2]; float4 w_pf;
        if (has) {
#pragma unroll
            for (int r = 0; r < 2; r++) {
                int idx = tid + r * 256;  // < 512 always
                int m = idx / (KB2 / 2), kp = idx % (KB2 / 2);
                a_pf[r] = *(const float2*)&g_theta[(rb * 128 + m) * K_ + k0n + 2 * kp];
            }
            int kk = tid / 32, c4 = tid % 32;
            int v = vbase + c4 * 4;
            if (v + 3 < V_) w_pf = *(const float4*)&bw[(size_t)(k0n + kk) * V_ + v];
            else {
                w_pf.x = (v     < V_) ? bw[(size_t)(k0n + kk) * V_ + v]     : 0.f;
                w_pf.y = (v + 1 < V_) ? bw[(size_t)(k0n + kk) * V_ + v + 1] : 0.f;
                w_pf.z = (v + 2 < V_) ? bw[(size_t)(k0n + kk) * V_ + v + 2] : 0.f;
                w_pf.w = 0.f;
            }
        }
        // compute on current tile
#pragma unroll
        for (int kp = 0; kp < KB2; kp += 2) {
            ulonglong2 ap[8];
#pragma unroll
            for (int i = 0; i < 8; i++)
                ap[i] = *(const ulonglong2*)&As2[cur][(ty * 8 + i) * KB2 + kp];
            ulonglong2 wA0 = *(const ulonglong2*)&Ws[cur][kp * 128 + tx * 8];
            ulonglong2 wA1 = *(const ulonglong2*)&Ws[cur][kp * 128 + tx * 8 + 4];
            ulonglong2 wB0 = *(const ulonglong2*)&Ws[cur][(kp + 1) * 128 + tx * 8];
            ulonglong2 wB1 = *(const ulonglong2*)&Ws[cur][(kp + 1) * 128 + tx * 8 + 4];
#pragma unroll
            for (int i = 0; i < 8; i++) {
                acc[i][0] = ffma2(ap[i].x, wA0.x, acc[i][0]);
                acc[i][1] = ffma2(ap[i].x, wA0.y, acc[i][1]);
                acc[i][2] = ffma2(ap[i].x, wA1.x, acc[i][2]);
                acc[i][3] = ffma2(ap[i].x, wA1.y, acc[i][3]);
                acc[i][0] = ffma2(ap[i].y, wB0.x, acc[i][0]);
                acc[i][1] = ffma2(ap[i].y, wB0.y, acc[i][1]);
                acc[i][2] = ffma2(ap[i].y, wB1.x, acc[i][2]);
                acc[i][3] = ffma2(ap[i].y, wB1.y, acc[i][3]);
            }
        }
        // commit prefetch
        if (has) {
#pragma unroll
            for (int r = 0; r < 2; r++) {
                int idx = tid + r * 256;
                int m = idx / (KB2 / 2), kp = idx % (KB2 / 2);
                As2[nxt][m * KB2 + 2 * kp]     = make_float2(a_pf[r].x, a_pf[r].x);
                As2[nxt][m * KB2 + 2 * kp + 1] = make_float2(a_pf[r].y, a_pf[r].y);
            }
            int kk = tid / 32, c4 = tid % 32;
            *(float4*)&Ws[nxt][kk * 128 + c4 * 4] = w_pf;
        }
        __syncthreads();
    }

    // epilogue: each thread owns 8 consecutive v at vbase + tx*8
    const int v0 = vbase + tx * 8;
    if (vbase + 128 <= V_) {
        float4 b0 = *(const float4*)&bb[v0];
        float4 b1 = *(const float4*)&bb[v0 + 4];
#pragma unroll
        for (int i = 0; i < 8; i++) {
            int row = rb * 128 + ty * 8 + i;
            float2 r0 = unpack2(acc[i][0]);
            float2 r1 = unpack2(acc[i][1]);
            float2 r2 = unpack2(acc[i][2]);
            float2 r3 = unpack2(acc[i][3]);
            float4 o0 = make_float4(r0.x + b0.x, r0.y + b0.y, r1.x + b0.z, r1.y + b0.w);
            float4 o1 = make_float4(r2.x + b1.x, r2.y + b1.y, r3.x + b1.z, r3.y + b1.w);
            *(float4*)&g_X[(size_t)row * V_ + v0]     = o0;
            *(float4*)&g_X[(size_t)row * V_ + v0 + 4] = o1;
        }
    } else {
#pragma unroll
        for (int i = 0; i < 8; i++) {
            int row = rb * 128 + ty * 8 + i;
#pragma unroll
            for (int j = 0; j < 4; j++) {
                float2 r = unpack2(acc[i][j]);
                int v = v0 + 2 * j;
                if (v < V_)     g_X[(size_t)row * V_ + v]     = r.x + bb[v];
                if (v + 1 < V_) g_X[(size_t)row * V_ + v + 1] = r.y + bb[v + 1];
            }
        }
    }
}

// token histogram (int atomics => deterministic); zero split in two launches
// so the ncu capture slot (4th launch) lands on k_gemm1.
__global__ void k_zero_a() {
    int i = blockIdx.x * blockDim.x + threadIdx.x;
    if (i < V_ / 2) g_cnt[i] = 0;
}
__global__ void k_zero_b() {
    int i = V_ / 2 + blockIdx.x * blockDim.x + threadIdx.x;
    if (i < V_) g_cnt[i] = 0;
}
__global__ void k_hist(const int* __restrict__ tok) {
    int i = blockIdx.x * blockDim.x + threadIdx.x;
    if (i < T_) atomicAdd(&g_cnt[tok[i]], 1);
}

// column stats over X -> per-column BN affine (a_v, c_v)
__global__ __launch_bounds__(256) void k_xstats(const float* __restrict__ bg,
                                                const float* __restrict__ bbb) {
    __shared__ float ss[8][32], sq[8][32];
    const int tx = threadIdx.x, ty = threadIdx.y;
    const int v  = blockIdx.x * 32 + tx;
    const bool ok = (v < V_);
    float s = 0.f, q = 0.f, x0 = 0.f;
    if (ok) {
        x0 = g_X[v];   // row-0 shift
        for (int b = ty; b < B_; b += 8) {
            float d = g_X[(size_t)b * V_ + v] - x0;
            s += d; q += d * d;
        }
    }
    ss[ty][tx] = s; sq[ty][tx] = q;
    __syncthreads();
    if (ty == 0 && ok) {
        float S = 0.f, Q = 0.f;
        for (int t = 0; t < 8; t++) { S += ss[t][tx]; Q += sq[t][tx]; }
        float mean_d = S * (1.f / B_);
        float var    = Q * (1.f / B_) - mean_d * mean_d;
        float mean   = x0 + mean_d;
        float a = bg[v] * rsqrtf(var + BN_EPS);
        g_av[v] = a;
        g_cv[v] = bbb[v] - a * mean;
    }
}

// fused pass: per row partials of  E = sum_v exp(y),  W = sum_v cnt_v * y
__global__ __launch_bounds__(512) void k_final() {
    __shared__ float sa[512], sc[512], scn[512];
    const int chunk = blockIdx.x;
    const int rg    = blockIdx.y;
    const int t     = threadIdx.x;
    const int v0    = chunk * 512;
    {
        int v = v0 + t;
        sa[t]  = (v < V_) ? g_av[v] : 0.f;
        sc[t]  = (v < V_) ? g_cv[v] : 0.f;
        scn[t] = (v < V_) ? (float)g_cnt[v] : 0.f;
    }
    __syncthreads();
    const int wrp  = t >> 5;
    const int lane = t & 31;
    const int b    = rg * 16 + wrp;
    const float* xr = g_X + (size_t)b * V_;
    float e = 0.f, wsum = 0.f;
#pragma unroll
    for (int j = 0; j < 16; j++) {
        int i = lane + j * 32;
        int v = v0 + i;
        if (v < V_) {
            float y = fmaf(sa[i], xr[v], sc[i]);
            e += exp_fast(y);
            wsum = fmaf(scn[i], y, wsum);
        }
    }
#pragma unroll
    for (int o = 16; o > 0; o >>= 1) {
        e    += __shfl_down_sync(0xffffffffu, e, o);
        wsum += __shfl_down_sync(0xffffffffu, wsum, o);
    }
    if (lane == 0) {
        g_ep[b * NC + chunk] = e;
        g_wp[b * NC + chunk] = wsum;
    }
}

// loglik[b] = W[b] - T * log(E[b])
__global__ void k_finish(float* __restrict__ out) {
    int b = blockIdx.x * blockDim.x + threadIdx.x;
    if (b >= B_) return;
    float E = 0.f, W = 0.f;
    for (int c = 0; c < NC; c++) { E += g_ep[b * NC + c]; W += g_wp[b * NC + c]; }
    out[b] = W - (float)T_ * logf(E);
}

extern "C" void kernel_launch(void* const* d_in, const int* in_sizes, int n_in,
                              void* d_out, int out_size) {
    const float* bows = (const float*)d_in[0];
    const float* eps  = (const float*)d_in[1];
    const int*   tok  = (const int*)  d_in[2];
    const float* fc1w = (const float*)d_in[3];
    const float* fc1b = (const float*)d_in[4];
    const float* fc2w = (const float*)d_in[5];
    const float* fc2b = (const float*)d_in[6];
    const float* muw  = (const float*)d_in[7];
    const float* mub  = (const float*)d_in[8];
    const float* bnmg = (const float*)d_in[9];
    const float* bnmb = (const float*)d_in[10];
    const float* sgw  = (const float*)d_in[11];
    const float* sgb  = (const float*)d_in[12];
    const float* bnsg = (const float*)d_in[13];
    const float* bnsb = (const float*)d_in[14];
    const float* btw  = (const float*)d_in[15];
    const float* btb  = (const float*)d_in[16];
    const float* bnbg = (const float*)d_in[17];
    const float* bnbb = (const float*)d_in[18];
    float* out = (float*)d_out;

    // independent prologue launches (slots 1-3) so slot 4 = k_gemm1 for ncu
    k_zero_a<<<(V_ / 2 + 255) / 256, 256>>>();
    k_zero_b<<<(V_ - V_ / 2 + 255) / 256, 256>>>();
    k_hist  <<<(T_ + 255) / 256, 256>>>(tok);

    k_gemm1 <<<dim3(S1, B_ / BM1), 224>>>(bows, fc1w);
    k_red1  <<<(B_ * H_ + 255) / 256, 256>>>(fc1b);
    k_h2    <<<(B_ * H_ + 255) / 256, 256>>>(fc2w, fc2b);
    k_musig <<<(2 * B_ * K_ + 255) / 256, 256>>>(muw, mub, sgw, sgb);
    k_bnk   <<<2 * K_, 256>>>(bnmg, bnmb, bnsg, bnsb);
    k_theta <<<(B_ * K_ + 255) / 256, 256>>>(eps);
    k_gemm2 <<<dim3((V_ + 127) / 128, B_ / 128), 256>>>(btw, btb);
    k_xstats<<<(V_ + 31) / 32, dim3(32, 8)>>>(bnbg, bnbb);
    k_final <<<dim3(NC, B_ / 16), 512>>>();
    k_finish<<<(B_ + 255) / 256, 256>>>(out);
}

// round 12
// speedup vs baseline: 2.3161x; 2.3161x over previous
#include <cuda_runtime.h>
#include <cuda_bf16.h>
#include <math.h>

#define B_ 1024
#define V_ 50000
#define H_ 100
#define K_ 200
#define T_ 32768
#define BN_EPS 1e-5f

// GEMM1 (bf16 mma): K'1 = 3*V = 150000 = 9375 slabs of 16; split-K 75 x 125
#define K1COLS 150000
#define S1 75
#define K1SLABS 125
// GEMM2: K'2 = 3*208 = 624 = 39 slabs
#define K2P 208
#define K2COLS 624
#define K2SLABS 39

#define NC 98

// ---------------- scratch (__device__ globals; no allocation) ----------------
__device__ __align__(16) __nv_bfloat16 g_A1[(size_t)B_ * K1COLS];   // 307 MB
__device__ __align__(16) __nv_bfloat16 g_B1[(size_t)K1COLS * 128];  // 38.4 MB
__device__ float g_p1[(size_t)S1 * B_ * 128];                       // 39.3 MB
__device__ __align__(16) __nv_bfloat16 g_A2[(size_t)B_ * K2COLS];
__device__ __align__(16) __nv_bfloat16 g_B2[(size_t)K2COLS * V_];   // 62.4 MB
__device__ float g_h1[B_ * H_];
__device__ float g_h2[B_ * H_];
__device__ float g_mulin[B_ * K_];
__device__ float g_siglin[B_ * K_];
__device__ float g_kA[2 * K_];
__device__ float g_kC[2 * K_];
__device__ float g_theta[B_ * K_];
__device__ float g_X[(size_t)B_ * V_];                              // 205 MB
__device__ float g_av[V_];
__device__ float g_cv[V_];
__device__ int   g_cnt[V_];
__device__ float g_ep[B_ * NC];
__device__ float g_wp[B_ * NC];

__device__ __forceinline__ float softplusf(float x) {
    return fmaxf(x, 0.0f) + log1pf(expf(-fabsf(x)));
}

// FMA-pipe exp (|y| <= ~40 here), rel err ~5e-8
__device__ __forceinline__ float exp_fast(float y) {
    const float LOG2E = 1.4426950408889634f;
    const float MAGIC = 12582912.0f;
    float t = y * LOG2E;
    float z = t + MAGIC;
    int   n = __float_as_int(z) - 0x4B400000;
    float f = t - (z - MAGIC);
    float p = 1.5252733e-5f;
    p = fmaf(p, f, 1.5403531e-4f);
    p = fmaf(p, f, 1.3333558e-3f);
    p = fmaf(p, f, 9.6181291e-3f);
    p = fmaf(p, f, 5.5504109e-2f);
    p = fmaf(p, f, 2.4022651e-1f);
    p = fmaf(p, f, 6.9314718e-1f);
    p = fmaf(p, f, 1.0f);
    return p * __int_as_float((n + 127) << 23);
}

// ---------------- mma helpers ----------------
__device__ __forceinline__ void ldsm4(unsigned& r0, unsigned& r1, unsigned& r2, unsigned& r3, unsigned addr) {
    asm volatile("ldmatrix.sync.aligned.m8n8.x4.shared.b16 {%0,%1,%2,%3}, [%4];"
        : "=r"(r0), "=r"(r1), "=r"(r2), "=r"(r3) : "r"(addr));
}
__device__ __forceinline__ void ldsm4t(unsigned& r0, unsigned& r1, unsigned& r2, unsigned& r3, unsigned addr) {
    asm volatile("ldmatrix.sync.aligned.m8n8.x4.trans.shared.b16 {%0,%1,%2,%3}, [%4];"
        : "=r"(r0), "=r"(r1), "=r"(r2), "=r"(r3) : "r"(addr));
}
__device__ __forceinline__ void mma16816(float (&c)[4], const unsigned (&a)[4], const unsigned (&b)[2]) {
    asm volatile("mma.sync.aligned.m16n8k16.row.col.f32.bf16.bf16.f32 "
        "{%0,%1,%2,%3}, {%4,%5,%6,%7}, {%8,%9}, {%0,%1,%2,%3};"
        : "+f"(c[0]), "+f"(c[1]), "+f"(c[2]), "+f"(c[3])
        : "r"(a[0]), "r"(a[1]), "r"(a[2]), "r"(a[3]), "r"(b[0]), "r"(b[1]));
}

// ---------------- prep kernels: bf16 hi/lo splits ----------------
// A1' = [bows_hi | bows_lo | bows_hi]  (1024 x 150000)
__global__ void k_prepA1(const float* __restrict__ bows) {
    size_t i = (size_t)blockIdx.x * blockDim.x + threadIdx.x;
    if (i >= (size_t)B_ * V_) return;
    size_t r = i / V_, c = i % V_;
    float x = bows[i];
    __nv_bfloat16 hi = __float2bfloat16(x);
    __nv_bfloat16 lo = __float2bfloat16(x - __bfloat162float(hi));
    __nv_bfloat16* row = g_A1 + r * (size_t)K1COLS;
    row[c] = hi; row[V_ + c] = lo; row[2 * (size_t)V_ + c] = hi;
}
// B1' = [w_hi ; w_hi ; w_lo]  (150000 x 128, cols>=100 zero)
__global__ void k_prepB1(const float* __restrict__ w) {
    size_t i = (size_t)blockIdx.x * blockDim.x + threadIdx.x;
    if (i >= (size_t)V_ * 128) return;
    size_t r = i / 128, h = i % 128;
    float x = (h < H_) ? w[r * H_ + h] : 0.f;
    __nv_bfloat16 hi = __float2bfloat16(x);
    __nv_bfloat16 lo = __float2bfloat16(x - __bfloat162float(hi));
    g_B1[r * 128 + h] = hi;
    g_B1[((size_t)V_ + r) * 128 + h] = hi;
    g_B1[(2 * (size_t)V_ + r) * 128 + h] = lo;
}
// A2' = [theta_hi | theta_lo | theta_hi]  (1024 x 624, k>=200 zero)
__global__ void k_prepA2() {
    int i = blockIdx.x * blockDim.x + threadIdx.x;
    if (i >= B_ * K2P) return;
    int r = i / K2P, k = i % K2P;
    float x = (k < K_) ? g_theta[r * K_ + k] : 0.f;
    __nv_bfloat16 hi = __float2bfloat16(x);
    __nv_bfloat16 lo = __float2bfloat16(x - __bfloat162float(hi));
    __nv_bfloat16* row = g_A2 + (size_t)r * K2COLS;
    row[k] = hi; row[K2P + k] = lo; row[2 * K2P + k] = hi;
}
// B2' = [bw_hi ; bw_hi ; bw_lo]  (624 x 50000, k>=200 zero)
__global__ void k_prepB2(const float* __restrict__ bw) {
    size_t i = (size_t)blockIdx.x * blockDim.x + threadIdx.x;
    if (i >= (size_t)K2P * V_) return;
    size_t r = i / V_, c = i % V_;
    float x = (r < K_) ? bw[r * V_ + c] : 0.f;
    __nv_bfloat16 hi = __float2bfloat16(x);
    __nv_bfloat16 lo = __float2bfloat16(x - __bfloat162float(hi));
    g_B2[r * V_ + c] = hi;
    g_B2[(K2P + r) * (size_t)V_ + c] = hi;
    g_B2[(2 * K2P + r) * (size_t)V_ + c] = lo;
}

// =====================================================================
// GEMM1 (mma): partials of A1'[B,K1] @ B1'[K1,128] -> g_p1[split][B][128]
// grid (S1, B/128), 256 thr (8 warps: 2 x 4), warp tile 64x32
// =====================================================================
__global__ __launch_bounds__(256) void k_gemm1m() {
    __shared__ __align__(16) unsigned char sA[2][4096]; // 128x16 bf16 swizzled
    __shared__ __align__(16) unsigned char sB[2][4096]; // 16x128 bf16 swizzled
    const int split = blockIdx.x, rb = blockIdx.y;
    const int tid = threadIdx.x, lane = tid & 31;
    const int wid = tid >> 5, wm = wid & 1, wn = wid >> 1;

    float acc[16][4];
#pragma unroll
    for (int i = 0; i < 16; i++)
#pragma unroll
        for (int j = 0; j < 4; j++) acc[i][j] = 0.f;

    // fill-thread roles
    const int fm = tid >> 1, fkh = tid & 1;                 // A: row, k-chunk
    const int fk = tid >> 4, fn8 = tid & 15;                // B: k-row, n-chunk
    const int dstA = fm * 32 + ((fkh ^ ((fm >> 2) & 1)) << 4);
    const int dstB = fk * 256 + ((fn8 ^ (fk & 7)) << 4);
    const size_t aRowOff = (size_t)(rb * 128 + fm) * K1COLS;
    const int slab0 = split * K1SLABS;

    // ldmatrix lane geometry
    const int sub = lane >> 3;
    const int arow_in = (lane & 7) + ((sub & 1) << 3);
    const int akh = sub >> 1;
    const int krow = (lane & 7) + ((sub & 1) << 3);

    // fill buffer 0
    *(uint4*)(sA[0] + dstA) = *(const uint4*)(g_A1 + aRowOff + (size_t)slab0 * 16 + fkh * 8);
    *(uint4*)(sB[0] + dstB) = *(const uint4*)(g_B1 + ((size_t)slab0 * 16 + fk) * 128 + fn8 * 8);
    __syncthreads();

    for (int ks = 0; ks < K1SLABS; ks++) {
        const int cur = ks & 1, nxt = cur ^ 1;
        const bool has = (ks + 1 < K1SLABS);
        uint4 pa, pb;
        if (has) {
            int sl = slab0 + ks + 1;
            pa = *(const uint4*)(g_A1 + aRowOff + (size_t)sl * 16 + fkh * 8);
            pb = *(const uint4*)(g_B1 + ((size_t)sl * 16 + fk) * 128 + fn8 * 8);
        }
        unsigned baseA = (unsigned)__cvta_generic_to_shared(&sA[cur][0]);
        unsigned baseB = (unsigned)__cvta_generic_to_shared(&sB[cur][0]);
        unsigned a[4][4], b[4][2];
#pragma unroll
        for (int mt = 0; mt < 4; mt++) {
            int r = wm * 64 + mt * 16 + arow_in;
            unsigned addr = baseA + r * 32 + ((akh ^ ((r >> 2) & 1)) << 4);
            ldsm4(a[mt][0], a[mt][1], a[mt][2], a[mt][3], addr);
        }
#pragma unroll
        for (int p = 0; p < 2; p++) {
            int n8 = wn * 4 + p * 2 + (sub >> 1);
            unsigned addr = baseB + krow * 256 + ((n8 ^ (krow & 7)) << 4);
            unsigned r0, r1, r2, r3;
            ldsm4t(r0, r1, r2, r3, addr);
            b[p * 2][0] = r0; b[p * 2][1] = r1;
            b[p * 2 + 1][0] = r2; b[p * 2 + 1][1] = r3;
        }
#pragma unroll
        for (int mt = 0; mt < 4; mt++)
#pragma unroll
            for (int nt = 0; nt < 4; nt++)
                mma16816(acc[mt * 4 + nt], a[mt], b[nt]);
        if (has) {
            *(uint4*)(sA[nxt] + dstA) = pa;
            *(uint4*)(sB[nxt] + dstB) = pb;
        }
        __syncthreads();
    }

    float* outp = g_p1 + (size_t)split * (B_ * 128);
#pragma unroll
    for (int mt = 0; mt < 4; mt++)
#pragma unroll
        for (int nt = 0; nt < 4; nt++) {
            float* f = acc[mt * 4 + nt];
            int r0 = rb * 128 + wm * 64 + mt * 16 + (lane >> 2);
            int c0 = wn * 32 + nt * 8 + ((lane & 3) << 1);
            *(float2*)&outp[(size_t)r0 * 128 + c0] = make_float2(f[0], f[1]);
            *(float2*)&outp[(size_t)(r0 + 8) * 128 + c0] = make_float2(f[2], f[3]);
        }
}

// =====================================================================
// GEMM2 (mma): X[B,V] = A2'[B,624] @ B2'[624,V] + beta_b
// grid (ceil(V/128)=391, B/128), 256 thr, warp tile 64x32
// =====================================================================
__global__ __launch_bounds__(256) void k_gemm2m(const float* __restrict__ bb) {
    __shared__ __align__(16) unsigned char sA[2][4096];
    __shared__ __align__(16) unsigned char sB[2][4096];
    const int cb = blockIdx.x, rb = blockIdx.y;
    const int vbase = cb * 128;
    const int tid = threadIdx.x, lane = tid & 31;
    const int wid = tid >> 5, wm = wid & 1, wn = wid >> 1;

    float acc[16][4];
#pragma unroll
    for (int i = 0; i < 16; i++)
#pragma unroll
        for (int j = 0; j < 4; j++) acc[i][j] = 0.f;

    const int fm = tid >> 1, fkh = tid & 1;
    const int fk = tid >> 4, fn8 = tid & 15;
    const int dstA = fm * 32 + ((fkh ^ ((fm >> 2) & 1)) << 4);
    const int dstB = fk * 256 + ((fn8 ^ (fk & 7)) << 4);
    const size_t aRowOff = (size_t)(rb * 128 + fm) * K2COLS;
    const bool bok = (vbase + fn8 * 8) < V_;

    const int sub = lane >> 3;
    const int arow_in = (lane & 7) + ((sub & 1) << 3);
    const int akh = sub >> 1;
    const int krow = (lane & 7) + ((sub & 1) << 3);

    uint4 zero4 = make_uint4(0, 0, 0, 0);
    *(uint4*)(sA[0] + dstA) = *(const uint4*)(g_A2 + aRowOff + fkh * 8);
    *(uint4*)(sB[0] + dstB) = bok ? *(const uint4*)(g_B2 + (size_t)fk * V_ + vbase + fn8 * 8) : zero4;
    __syncthreads();

    for (int ks = 0; ks < K2SLABS; ks++) {
        const int cur = ks & 1, nxt = cur ^ 1;
        const bool has = (ks + 1 < K2SLABS);
        uint4 pa, pb;
        if (has) {
            int sl = ks + 1;
            pa = *(const uint4*)(g_A2 + aRowOff + (size_t)sl * 16 + fkh * 8);
            pb = bok ? *(const uint4*)(g_B2 + ((size_t)sl * 16 + fk) * V_ + vbase + fn8 * 8) : zero4;
        }
        unsigned baseA = (unsigned)__cvta_generic_to_shared(&sA[cur][0]);
        unsigned baseB = (unsigned)__cvta_generic_to_shared(&sB[cur][0]);
        unsigned a[4][4], b[4][2];
#pragma unroll
        for (int mt = 0; mt < 4; mt++) {
            int r = wm * 64 + mt * 16 + arow_in;
            unsigned addr = baseA + r * 32 + ((akh ^ ((r >> 2) & 1)) << 4);
            ldsm4(a[mt][0], a[mt][1], a[mt][2], a[mt][3], addr);
        }
#pragma unroll
        for (int p = 0; p < 2; p++) {
            int n8 = wn * 4 + p * 2 + (sub >> 1);
            unsigned addr = baseB + krow * 256 + ((n8 ^ (krow & 7)) << 4);
            unsigned r0, r1, r2, r3;
            ldsm4t(r0, r1, r2, r3, addr);
            b[p * 2][0] = r0; b[p * 2][1] = r1;
            b[p * 2 + 1][0] = r2; b[p * 2 + 1][1] = r3;
        }
#pragma unroll
        for (int mt = 0; mt < 4; mt++)
#pragma unroll
            for (int nt = 0; nt < 4; nt++)
                mma16816(acc[mt * 4 + nt], a[mt], b[nt]);
        if (has) {
            *(uint4*)(sA[nxt] + dstA) = pa;
            *(uint4*)(sB[nxt] + dstB) = pb;
        }
        __syncthreads();
    }

#pragma unroll
    for (int mt = 0; mt < 4; mt++)
#pragma unroll
        for (int nt = 0; nt < 4; nt++) {
            float* f = acc[mt * 4 + nt];
            int gr = rb * 128 + wm * 64 + mt * 16 + (lane >> 2);
            int gc = vbase + wn * 32 + nt * 8 + ((lane & 3) << 1);
            if (gc < V_) {
                float2 bias = *(const float2*)&bb[gc];
                *(float2*)&g_X[(size_t)gr * V_ + gc] = make_float2(f[0] + bias.x, f[1] + bias.y);
                *(float2*)&g_X[(size_t)(gr + 8) * V_ + gc] = make_float2(f[2] + bias.x, f[3] + bias.y);
            }
        }
}

// ---------------- small kernels (unchanged math from passing R5 build) ----------------
__global__ void k_red1(const float* __restrict__ b1) {
    int i = blockIdx.x * blockDim.x + threadIdx.x;
    if (i >= B_ * H_) return;
    int b = i / H_, h = i % H_;
    float s = 0.f;
    for (int t = 0; t < S1; t++) s += g_p1[(size_t)t * (B_ * 128) + (size_t)b * 128 + h];
    s += b1[h];
    g_h1[i] = softplusf(s);
}

__global__ void k_h2(const float* __restrict__ w2, const float* __restrict__ b2) {
    int i = blockIdx.x * blockDim.x + threadIdx.x;
    if (i >= B_ * H_) return;
    int b = i / H_, h = i % H_;
    const float* hr = g_h1 + b * H_;
    float s = b2[h];
    for (int j = 0; j < H_; j++) s = fmaf(hr[j], w2[j * H_ + h], s);
    g_h2[i] = softplusf(s);
}

__global__ void k_musig(const float* __restrict__ muw, const float* __restrict__ mub,
                        const float* __restrict__ sgw, const float* __restrict__ sgb) {
    int i = blockIdx.x * blockDim.x + threadIdx.x;
    if (i >= 2 * B_ * K_) return;
    int which = i / (B_ * K_);
    int r = i % (B_ * K_);
    int b = r / K_, k = r % K_;
    const float* hr = g_h2 + b * H_;
    const float* w  = which ? sgw : muw;
    float s = which ? sgb[k] : mub[k];
    for (int j = 0; j < H_; j++) s = fmaf(hr[j], w[j * K_ + k], s);
    (which ? g_siglin : g_mulin)[b * K_ + k] = s;
}

__global__ __launch_bounds__(256) void k_bnk(const float* __restrict__ mug, const float* __restrict__ mubb,
                                             const float* __restrict__ sgg, const float* __restrict__ sgbb) {
    __shared__ float ssum[256], ssq[256];
    int col = blockIdx.x;
    int c = (col < K_) ? col : col - K_;
    const float* x = (col < K_) ? g_mulin : g_siglin;
    float x0 = x[c];
    float s = 0.f, q = 0.f;
    for (int b = threadIdx.x; b < B_; b += 256) {
        float d = x[b * K_ + c] - x0;
        s += d; q += d * d;
    }
    ssum[threadIdx.x] = s; ssq[threadIdx.x] = q;
    __syncthreads();
    for (int o = 128; o > 0; o >>= 1) {
        if (threadIdx.x < o) {
            ssum[threadIdx.x] += ssum[threadIdx.x + o];
            ssq[threadIdx.x]  += ssq[threadIdx.x + o];
        }
        __syncthreads();
    }
    if (threadIdx.x == 0) {
        float mean_d = ssum[0] * (1.f / B_);
        float var    = ssq[0] * (1.f / B_) - mean_d * mean_d;
        float mean   = x0 + mean_d;
        float g  = (col < K_) ? mug[c]  : sgg[c];
        float bbv = (col < K_) ? mubb[c] : sgbb[c];
        float a  = g * rsqrtf(var + BN_EPS);
        g_kA[col] = a;
        g_kC[col] = bbv - a * mean;
    }
}

__global__ void k_theta(const float* __restrict__ eps) {
    int i = blockIdx.x * blockDim.x + threadIdx.x;
    if (i >= B_ * K_) return;
    int k = i % K_;
    float m  = fmaf(g_kA[k], g_mulin[i], g_kC[k]);
    float sg = expf(0.5f * fmaf(g_kA[K_ + k], g_siglin[i], g_kC[K_ + k]));
    g_theta[i] = expf(fmaf(sg, eps[i], m));
}

__global__ void k_zero() {
    int i = blockIdx.x * blockDim.x + threadIdx.x;
    if (i < V_) g_cnt[i] = 0;
}
__global__ void k_hist(const int* __restrict__ tok) {
    int i = blockIdx.x * blockDim.x + threadIdx.x;
    if (i < T_) atomicAdd(&g_cnt[tok[i]], 1);
}

__global__ __launch_bounds__(256) void k_xstats(const float* __restrict__ bg,
                                                const float* __restrict__ bbb) {
    __shared__ float ss[8][32], sq[8][32];
    const int tx = threadIdx.x, ty = threadIdx.y;
    const int v  = blockIdx.x * 32 + tx;
    const bool ok = (v < V_);
    float s = 0.f, q = 0.f, x0 = 0.f;
    if (ok) {
        x0 = g_X[v];
        for (int b = ty; b < B_; b += 8) {
            float d = g_X[(size_t)b * V_ + v] - x0;
            s += d; q += d * d;
        }
    }
    ss[ty][tx] = s; sq[ty][tx] = q;
    __syncthreads();
    if (ty == 0 && ok) {
        float S = 0.f, Q = 0.f;
        for (int t = 0; t < 8; t++) { S += ss[t][tx]; Q += sq[t][tx]; }
        float mean_d = S * (1.f / B_);
        float var    = Q * (1.f / B_) - mean_d * mean_d;
        float mean   = x0 + mean_d;
        float a = bg[v] * rsqrtf(var + BN_EPS);
        g_av[v] = a;
        g_cv[v] = bbb[v] - a * mean;
    }
}

__global__ __launch_bounds__(512) void k_final() {
    __shared__ float sa[512], sc[512], scn[512];
    const int chunk = blockIdx.x;
    const int rg    = blockIdx.y;
    const int t     = threadIdx.x;
    const int v0    = chunk * 512;
    {
        int v = v0 + t;
        sa[t]  = (v < V_) ? g_av[v] : 0.f;
        sc[t]  = (v < V_) ? g_cv[v] : 0.f;
        scn[t] = (v < V_) ? (float)g_cnt[v] : 0.f;
    }
    __syncthreads();
    const int wrp  = t >> 5;
    const int lane = t & 31;
    const int b    = rg * 16 + wrp;
    const float* xr = g_X + (size_t)b * V_;
    float e = 0.f, wsum = 0.f;
#pragma unroll
    for (int j = 0; j < 16; j++) {
        int i = lane + j * 32;
        int v = v0 + i;
        if (v < V_) {
            float y = fmaf(sa[i], xr[v], sc[i]);
            e += exp_fast(y);
            wsum = fmaf(scn[i], y, wsum);
        }
    }
#pragma unroll
    for (int o = 16; o > 0; o >>= 1) {
        e    += __shfl_down_sync(0xffffffffu, e, o);
        wsum += __shfl_down_sync(0xffffffffu, wsum, o);
    }
    if (lane == 0) {
        g_ep[b * NC + chunk] = e;
        g_wp[b * NC + chunk] = wsum;
    }
}

__global__ void k_finish(float* __restrict__ out) {
    int b = blockIdx.x * blockDim.x + threadIdx.x;
    if (b >= B_) return;
    float E = 0.f, W = 0.f;
    for (int c = 0; c < NC; c++) { E += g_ep[b * NC + c]; W += g_wp[b * NC + c]; }
    out[b] = W - (float)T_ * logf(E);
}

extern "C" void kernel_launch(void* const* d_in, const int* in_sizes, int n_in,
                              void* d_out, int out_size) {
    const float* bows = (const float*)d_in[0];
    const float* eps  = (const float*)d_in[1];
    const int*   tok  = (const int*)  d_in[2];
    const float* fc1w = (const float*)d_in[3];
    const float* fc1b = (const float*)d_in[4];
    const float* fc2w = (const float*)d_in[5];
    const float* fc2b = (const float*)d_in[6];
    const float* muw  = (const float*)d_in[7];
    const float* mub  = (const float*)d_in[8];
    const float* bnmg = (const float*)d_in[9];
    const float* bnmb = (const float*)d_in[10];
    const float* sgw  = (const float*)d_in[11];
    const float* sgb  = (const float*)d_in[12];
    const float* bnsg = (const float*)d_in[13];
    const float* bnsb = (const float*)d_in[14];
    const float* btw  = (const float*)d_in[15];
    const float* btb  = (const float*)d_in[16];
    const float* bnbg = (const float*)d_in[17];
    const float* bnbb = (const float*)d_in[18];
    float* out = (float*)d_out;

    // order chosen so the ncu capture slot (4th launch) = k_gemm1m
    k_prepA1<<<(int)(((size_t)B_ * V_ + 255) / 256), 256>>>(bows);
    k_prepB1<<<(int)(((size_t)V_ * 128 + 255) / 256), 256>>>(fc1w);
    k_zero  <<<(V_ + 255) / 256, 256>>>();
    k_gemm1m<<<dim3(S1, B_ / 128), 256>>>();
    k_hist  <<<(T_ + 255) / 256, 256>>>(tok);
    k_red1  <<<(B_ * H_ + 255) / 256, 256>>>(fc1b);
    k_h2    <<<(B_ * H_ + 255) / 256, 256>>>(fc2w, fc2b);
    k_musig <<<(2 * B_ * K_ + 255) / 256, 256>>>(muw, mub, sgw, sgb);
    k_bnk   <<<2 * K_, 256>>>(bnmg, bnmb, bnsg, bnsb);
    k_theta <<<(B_ * K_ + 255) / 256, 256>>>(eps);
    k_prepA2<<<(B_ * K2P + 255) / 256, 256>>>();
    k_prepB2<<<(int)(((size_t)K2P * V_ + 255) / 256), 256>>>(btw);
    k_gemm2m<<<dim3((V_ + 127) / 128, B_ / 128), 256>>>(btb);
    k_xstats<<<(V_ + 31) / 32, dim3(32, 8)>>>(bnbg, bnbb);
    k_final <<<dim3(NC, B_ / 16), 512>>>();
    k_finish<<<(B_ + 255) / 256, 256>>>(out);
}

// round 16
// speedup vs baseline: 2.7359x; 1.1813x over previous
#include <cuda_runtime.h>
#include <cuda_bf16.h>
#include <math.h>

#define B_ 1024
#define V_ 50000
#define H_ 100
#define K_ 200
#define T_ 32768
#define BN_EPS 1e-5f

// GEMM1: K'1 padded 150000 -> 153600 = 75 splits x 2048; stage KS=64 -> 32 stages
#define K1P 153600
#define S1 75
#define KDEPTH1 2048
#define NST1 32
// GEMM2: K'2 padded 624 -> 640; 10 stages
#define K2P 208
#define K2PAD 640
#define NST2 10
#define KS 64

#define NC 98

// ---------------- scratch (__device__ globals; no allocation) ----------------
__device__ __align__(16) __nv_bfloat16 g_A1[(size_t)B_ * K1P];      // 314.6 MB
__device__ __align__(16) __nv_bfloat16 g_B1[(size_t)K1P * 128];     // 39.3 MB
__device__ float g_p1[(size_t)S1 * B_ * 128];                       // 39.3 MB
__device__ __align__(16) __nv_bfloat16 g_A2[(size_t)B_ * K2PAD];
__device__ __align__(16) __nv_bfloat16 g_B2[(size_t)K2PAD * V_];    // 64 MB
__device__ float g_h1[B_ * H_];
__device__ float g_h2[B_ * H_];
__device__ float g_mulin[B_ * K_];
__device__ float g_siglin[B_ * K_];
__device__ float g_kA[2 * K_];
__device__ float g_kC[2 * K_];
__device__ float g_theta[B_ * K_];
__device__ float g_X[(size_t)B_ * V_];                              // 205 MB
__device__ float g_av[V_];
__device__ float g_cv[V_];
__device__ int   g_cnt[V_];
__device__ float g_ep[B_ * NC];
__device__ float g_wp[B_ * NC];

__device__ __forceinline__ float softplusf(float x) {
    return fmaxf(x, 0.0f) + log1pf(expf(-fabsf(x)));
}

__device__ __forceinline__ float exp_fast(float y) {
    const float LOG2E = 1.4426950408889634f;
    const float MAGIC = 12582912.0f;
    float t = y * LOG2E;
    float z = t + MAGIC;
    int   n = __float_as_int(z) - 0x4B400000;
    float f = t - (z - MAGIC);
    float p = 1.5252733e-5f;
    p = fmaf(p, f, 1.5403531e-4f);
    p = fmaf(p, f, 1.3333558e-3f);
    p = fmaf(p, f, 9.6181291e-3f);
    p = fmaf(p, f, 5.5504109e-2f);
    p = fmaf(p, f, 2.4022651e-1f);
    p = fmaf(p, f, 6.9314718e-1f);
    p = fmaf(p, f, 1.0f);
    return p * __int_as_float((n + 127) << 23);
}

// ---------------- mma / cp.async helpers ----------------
__device__ __forceinline__ void ldsm4(unsigned& r0, unsigned& r1, unsigned& r2, unsigned& r3, unsigned addr) {
    asm volatile("ldmatrix.sync.aligned.m8n8.x4.shared.b16 {%0,%1,%2,%3}, [%4];"
        : "=r"(r0), "=r"(r1), "=r"(r2), "=r"(r3) : "r"(addr));
}
__device__ __forceinline__ void ldsm4t(unsigned& r0, unsigned& r1, unsigned& r2, unsigned& r3, unsigned addr) {
    asm volatile("ldmatrix.sync.aligned.m8n8.x4.trans.shared.b16 {%0,%1,%2,%3}, [%4];"
        : "=r"(r0), "=r"(r1), "=r"(r2), "=r"(r3) : "r"(addr));
}
__device__ __forceinline__ void mma16816(float (&c)[4], const unsigned (&a)[4], const unsigned (&b)[2]) {
    asm volatile("mma.sync.aligned.m16n8k16.row.col.f32.bf16.bf16.f32 "
        "{%0,%1,%2,%3}, {%4,%5,%6,%7}, {%8,%9}, {%0,%1,%2,%3};"
        : "+f"(c[0]), "+f"(c[1]), "+f"(c[2]), "+f"(c[3])
        : "r"(a[0]), "r"(a[1]), "r"(a[2]), "r"(a[3]), "r"(b[0]), "r"(b[1]));
}
__device__ __forceinline__ void cp16(unsigned dst, const void* src) {
    asm volatile("cp.async.cg.shared.global [%0], [%1], 16;" :: "r"(dst), "l"(src));
}
#define CP_COMMIT() asm volatile("cp.async.commit_group;")
#define CP_WAIT0()  asm volatile("cp.async.wait_group 0;")

// ---------------- prep kernels: bf16 hi/lo splits ----------------
// A1' rows: [hi(0..V) | lo | hi], stride K1P
__global__ void k_prepA1(const float* __restrict__ bows) {
    size_t i = (size_t)blockIdx.x * blockDim.x + threadIdx.x;
    if (i >= (size_t)B_ * V_) return;
    size_t r = i / V_, c = i % V_;
    float x = bows[i];
    __nv_bfloat16 hi = __float2bfloat16(x);
    __nv_bfloat16 lo = __float2bfloat16(x - __bfloat162float(hi));
    __nv_bfloat16* row = g_A1 + r * (size_t)K1P;
    row[c] = hi; row[V_ + c] = lo; row[2 * (size_t)V_ + c] = hi;
}
// B1' rows: [hi ; hi ; lo], 128-wide (cols >= H zero)
__global__ void k_prepB1(const float* __restrict__ w) {
    size_t i = (size_t)blockIdx.x * blockDim.x + threadIdx.x;
    if (i >= (size_t)V_ * 128) return;
    size_t r = i / 128, h = i % 128;
    float x = (h < H_) ? w[r * H_ + h] : 0.f;
    __nv_bfloat16 hi = __float2bfloat16(x);
    __nv_bfloat16 lo = __float2bfloat16(x - __bfloat162float(hi));
    g_B1[r * 128 + h] = hi;
    g_B1[((size_t)V_ + r) * 128 + h] = hi;
    g_B1[(2 * (size_t)V_ + r) * 128 + h] = lo;
}
// zero K pads of A1 (per-row tail) and B1 (tail rows)
__global__ void k_pad1() {
    int i = blockIdx.x * blockDim.x + threadIdx.x;
    const int APAD = B_ * (K1P - 3 * V_);           // 1024*3600
    if (i < APAD) {
        int row = i / (K1P - 3 * V_), c = i % (K1P - 3 * V_);
        g_A1[(size_t)row * K1P + 3 * (size_t)V_ + c] = __float2bfloat16(0.f);
    } else {
        int j = i - APAD;
        if (j < (K1P - 3 * V_) * 128) {
            int r = j / 128, h = j % 128;
            g_B1[(size_t)(3 * (size_t)V_ + r) * 128 + h] = __float2bfloat16(0.f);
        }
    }
}
// A2' rows: k<624: region [hi|lo|hi] of theta (208 each, 200 valid); k>=624: 0
__global__ void k_prepA2() {
    int i = blockIdx.x * blockDim.x + threadIdx.x;
    if (i >= B_ * K2PAD) return;
    int r = i / K2PAD, k = i % K2PAD;
    __nv_bfloat16 out = __float2bfloat16(0.f);
    if (k < 3 * K2P) {
        int reg = k / K2P, kk = k % K2P;
        float x = (kk < K_) ? g_theta[r * K_ + kk] : 0.f;
        __nv_bfloat16 hi = __float2bfloat16(x);
        if (reg == 1) out = __float2bfloat16(x - __bfloat162float(hi));
        else out = hi;
    }
    g_A2[(size_t)r * K2PAD + k] = out;
}
// B2' rows: r<624: region [hi;hi;lo] of bw; r>=624: 0
__global__ void k_prepB2(const float* __restrict__ bw) {
    size_t i = (size_t)blockIdx.x * blockDim.x + threadIdx.x;
    if (i >= (size_t)K2PAD * V_) return;
    size_t r = i / V_, c = i % V_;
    __nv_bfloat16 out = __float2bfloat16(0.f);
    if (r < 3 * K2P) {
        int reg = (int)(r / K2P), rr = (int)(r % K2P);
        float x = (rr < K_) ? bw[(size_t)rr * V_ + c] : 0.f;
        __nv_bfloat16 hi = __float2bfloat16(x);
        if (reg == 2) out = __float2bfloat16(x - __bfloat162float(hi));
        else out = hi;
    }
    g_B2[r * V_ + c] = out;
}

// =====================================================================
// GEMM1 (mma, cp.async, KS=64): partials of A1'[B,K1P] @ B1'[K1P,128]
// grid (S1, B/128), 256 thr (8 warps 2x4), warp tile 64x32
// smem: dynamic 64KB: sA[2] 16KB (128r x 64k), sB[2] 16KB (64k x 128n)
// =====================================================================
__global__ __launch_bounds__(256) void k_gemm1m() {
    extern __shared__ unsigned char smem[];
    unsigned char* sAp[2] = { smem, smem + 16384 };
    unsigned char* sBp[2] = { smem + 32768, smem + 49152 };
    const int split = blockIdx.x, rb = blockIdx.y;
    const int tid = threadIdx.x, lane = tid & 31;
    const int wid = tid >> 5, wm = wid & 1, wn = wid >> 1;

    float acc[16][4];
#pragma unroll
    for (int i = 0; i < 16; i++)
#pragma unroll
        for (int j = 0; j < 4; j++) acc[i][j] = 0.f;

    // fill roles: A 2 thr/row x 4 chunks; B 4 thr/row x 4 chunks
    const int am = tid >> 1, ac0 = (tid & 1) * 4;
    const size_t aRow = (size_t)(rb * 128 + am) * K1P;
    const int bkr = tid >> 2, bc0 = tid & 3;

    const int arow_in = (lane & 7) + (((lane >> 3) & 1) << 3);
    const int khsel = lane >> 4;
    const int kbase = split * KDEPTH1;

    {
        unsigned uA = (unsigned)__cvta_generic_to_shared(sAp[0]);
        unsigned uB = (unsigned)__cvta_generic_to_shared(sBp[0]);
#pragma unroll
        for (int j = 0; j < 4; j++) {
            int c = ac0 + j;
            cp16(uA + am * 128 + (((c ^ (am & 7))) << 4), g_A1 + aRow + kbase + c * 8);
        }
#pragma unroll
        for (int j = 0; j < 4; j++) {
            int c = bc0 + j * 4;
            int phys = (c & 8) | ((c ^ bkr) & 7);
            cp16(uB + bkr * 256 + (phys << 4), g_B1 + (size_t)(kbase + bkr) * 128 + c * 8);
        }
        CP_COMMIT(); CP_WAIT0();
    }
    __syncthreads();

    for (int ks = 0; ks < NST1; ks++) {
        const int cur = ks & 1, nxt = cur ^ 1;
        const bool has = (ks + 1 < NST1);
        if (has) {
            int k0 = kbase + (ks + 1) * KS;
            unsigned uA = (unsigned)__cvta_generic_to_shared(sAp[nxt]);
            unsigned uB = (unsigned)__cvta_generic_to_shared(sBp[nxt]);
#pragma unroll
            for (int j = 0; j < 4; j++) {
                int c = ac0 + j;
                cp16(uA + am * 128 + ((c ^ (am & 7)) << 4), g_A1 + aRow + k0 + c * 8);
            }
#pragma unroll
            for (int j = 0; j < 4; j++) {
                int c = bc0 + j * 4;
                int phys = (c & 8) | ((c ^ bkr) & 7);
                cp16(uB + bkr * 256 + (phys << 4), g_B1 + (size_t)(k0 + bkr) * 128 + c * 8);
            }
            CP_COMMIT();
        }
        unsigned baseA = (unsigned)__cvta_generic_to_shared(sAp[cur]);
        unsigned baseB = (unsigned)__cvta_generic_to_shared(sBp[cur]);
#pragma unroll
        for (int kg = 0; kg < 4; kg++) {
            unsigned a[4][4], b[4][2];
#pragma unroll
            for (int mt = 0; mt < 4; mt++) {
                int r = wm * 64 + mt * 16 + arow_in;
                int c = kg * 2 + khsel;
                ldsm4(a[mt][0], a[mt][1], a[mt][2], a[mt][3],
                      baseA + r * 128 + ((c ^ (r & 7)) << 4));
            }
#pragma unroll
            for (int p = 0; p < 2; p++) {
                int kr = kg * 16 + arow_in;
                int c = wn * 4 + p * 2 + khsel;
                int phys = (c & 8) | ((c ^ kr) & 7);
                unsigned r0, r1, r2, r3;
                ldsm4t(r0, r1, r2, r3, baseB + kr * 256 + (phys << 4));
                b[p * 2][0] = r0; b[p * 2][1] = r1;
                b[p * 2 + 1][0] = r2; b[p * 2 + 1][1] = r3;
            }
#pragma unroll
            for (int mt = 0; mt < 4; mt++)
#pragma unroll
                for (int nt = 0; nt < 4; nt++)
                    mma16816(acc[mt * 4 + nt], a[mt], b[nt]);
        }
        if (has) CP_WAIT0();
        __syncthreads();
    }

    float* outp = g_p1 + (size_t)split * (B_ * 128);
#pragma unroll
    for (int mt = 0; mt < 4; mt++)
#pragma unroll
        for (int nt = 0; nt < 4; nt++) {
            float* f = acc[mt * 4 + nt];
            int r0 = rb * 128 + wm * 64 + mt * 16 + (lane >> 2);
            int c0 = wn * 32 + nt * 8 + ((lane & 3) << 1);
            *(float2*)&outp[(size_t)r0 * 128 + c0] = make_float2(f[0], f[1]);
            *(float2*)&outp[(size_t)(r0 + 8) * 128 + c0] = make_float2(f[2], f[3]);
        }
}

// =====================================================================
// GEMM2 (mma, cp.async, KS=64): X[B,V] = A2'[B,640] @ B2'[640,V] + beta_b
// grid (391, 8), 256 thr
// =====================================================================
__global__ __launch_bounds__(256) void k_gemm2m(const float* __restrict__ bb) {
    extern __shared__ unsigned char smem[];
    unsigned char* sAp[2] = { smem, smem + 16384 };
    unsigned char* sBp[2] = { smem + 32768, smem + 49152 };
    const int cb = blockIdx.x, rb = blockIdx.y;
    const int vbase = cb * 128;
    const int tid = threadIdx.x, lane = tid & 31;
    const int wid = tid >> 5, wm = wid & 1, wn = wid >> 1;

    float acc[16][4];
#pragma unroll
    for (int i = 0; i < 16; i++)
#pragma unroll
        for (int j = 0; j < 4; j++) acc[i][j] = 0.f;

    const int am = tid >> 1, ac0 = (tid & 1) * 4;
    const size_t aRow = (size_t)(rb * 128 + am) * K2PAD;
    const int bkr = tid >> 2, bc0 = tid & 3;

    const int arow_in = (lane & 7) + (((lane >> 3) & 1) << 3);
    const int khsel = lane >> 4;
    const uint4 zero4 = make_uint4(0, 0, 0, 0);

    {
        unsigned uA = (unsigned)__cvta_generic_to_shared(sAp[0]);
        unsigned uB = (unsigned)__cvta_generic_to_shared(sBp[0]);
#pragma unroll
        for (int j = 0; j < 4; j++) {
            int c = ac0 + j;
            cp16(uA + am * 128 + ((c ^ (am & 7)) << 4), g_A2 + aRow + c * 8);
        }
#pragma unroll
        for (int j = 0; j < 4; j++) {
            int c = bc0 + j * 4;
            int phys = (c & 8) | ((c ^ bkr) & 7);
            int col = vbase + c * 8;
            if (col < V_) cp16(uB + bkr * 256 + (phys << 4), g_B2 + (size_t)bkr * V_ + col);
            else *(uint4*)(sBp[0] + bkr * 256 + (phys << 4)) = zero4;
        }
        CP_COMMIT(); CP_WAIT0();
    }
    __syncthreads();

    for (int ks = 0; ks < NST2; ks++) {
        const int cur = ks & 1, nxt = cur ^ 1;
        const bool has = (ks + 1 < NST2);
        if (has) {
            int k0 = (ks + 1) * KS;
            unsigned uA = (unsigned)__cvta_generic_to_shared(sAp[nxt]);
            unsigned uB = (unsigned)__cvta_generic_to_shared(sBp[nxt]);
#pragma unroll
            for (int j = 0; j < 4; j++) {
                int c = ac0 + j;
                cp16(uA + am * 128 + ((c ^ (am & 7)) << 4), g_A2 + aRow + k0 + c * 8);
            }
#pragma unroll
            for (int j = 0; j < 4; j++) {
                int c = bc0 + j * 4;
                int phys = (c & 8) | ((c ^ bkr) & 7);
                int col = vbase + c * 8;
                if (col < V_) cp16(uB + bkr * 256 + (phys << 4), g_B2 + (size_t)(k0 + bkr) * V_ + col);
                else *(uint4*)(sBp[nxt] + bkr * 256 + (phys << 4)) = zero4;
            }
            CP_COMMIT();
        }
        unsigned baseA = (unsigned)__cvta_generic_to_shared(sAp[cur]);
        unsigned baseB = (unsigned)__cvta_generic_to_shared(sBp[cur]);
#pragma unroll
        for (int kg = 0; kg < 4; kg++) {
            unsigned a[4][4], b[4][2];
#pragma unroll
            for (int mt = 0; mt < 4; mt++) {
                int r = wm * 64 + mt * 16 + arow_in;
                int c = kg * 2 + khsel;
                ldsm4(a[mt][0], a[mt][1], a[mt][2], a[mt][3],
                      baseA + r * 128 + ((c ^ (r & 7)) << 4));
            }
#pragma unroll
            for (int p = 0; p < 2; p++) {
                int kr = kg * 16 + arow_in;
                int c = wn * 4 + p * 2 + khsel;
                int phys = (c & 8) | ((c ^ kr) & 7);
                unsigned r0, r1, r2, r3;
                ldsm4t(r0, r1, r2, r3, baseB + kr * 256 + (phys << 4));
                b[p * 2][0] = r0; b[p * 2][1] = r1;
                b[p * 2 + 1][0] = r2; b[p * 2 + 1][1] = r3;
            }
#pragma unroll
            for (int mt = 0; mt < 4; mt++)
#pragma unroll
                for (int nt = 0; nt < 4; nt++)
                    mma16816(acc[mt * 4 + nt], a[mt], b[nt]);
        }
        if (has) CP_WAIT0();
        __syncthreads();
    }

#pragma unroll
    for (int mt = 0; mt < 4; mt++)
#pragma unroll
        for (int nt = 0; nt < 4; nt++) {
            float* f = acc[mt * 4 + nt];
            int gr = rb * 128 + wm * 64 + mt * 16 + (lane >> 2);
            int gc = vbase + wn * 32 + nt * 8 + ((lane & 3) << 1);
            if (gc < V_) {
                float2 bias = *(const float2*)&bb[gc];
                *(float2*)&g_X[(size_t)gr * V_ + gc] = make_float2(f[0] + bias.x, f[1] + bias.y);
                *(float2*)&g_X[(size_t)(gr + 8) * V_ + gc] = make_float2(f[2] + bias.x, f[3] + bias.y);
            }
        }
}

// ---------------- small kernels (math unchanged from passing R12 build) ----------------
__global__ void k_red1(const float* __restrict__ b1) {
    int i = blockIdx.x * blockDim.x + threadIdx.x;
    if (i >= B_ * H_) return;
    int b = i / H_, h = i % H_;
    float s = 0.f;
    for (int t = 0; t < S1; t++) s += g_p1[(size_t)t * (B_ * 128) + (size_t)b * 128 + h];
    s += b1[h];
    g_h1[i] = softplusf(s);
}

__global__ void k_h2(const float* __restrict__ w2, const float* __restrict__ b2) {
    int i = blockIdx.x * blockDim.x + threadIdx.x;
    if (i >= B_ * H_) return;
    int b = i / H_, h = i % H_;
    const float* hr = g_h1 + b * H_;
    float s = b2[h];
    for (int j = 0; j < H_; j++) s = fmaf(hr[j], w2[j * H_ + h], s);
    g_h2[i] = softplusf(s);
}

__global__ void k_musig(const float* __restrict__ muw, const float* __restrict__ mub,
                        const float* __restrict__ sgw, const float* __restrict__ sgb) {
    int i = blockIdx.x * blockDim.x + threadIdx.x;
    if (i >= 2 * B_ * K_) return;
    int which = i / (B_ * K_);
    int r = i % (B_ * K_);
    int b = r / K_, k = r % K_;
    const float* hr = g_h2 + b * H_;
    const float* w  = which ? sgw : muw;
    float s = which ? sgb[k] : mub[k];
    for (int j = 0; j < H_; j++) s = fmaf(hr[j], w[j * K_ + k], s);
    (which ? g_siglin : g_mulin)[b * K_ + k] = s;
}

__global__ __launch_bounds__(256) void k_bnk(const float* __restrict__ mug, const float* __restrict__ mubb,
                                             const float* __restrict__ sgg, const float* __restrict__ sgbb) {
    __shared__ float ssum[256], ssq[256];
    int col = blockIdx.x;
    int c = (col < K_) ? col : col - K_;
    const float* x = (col < K_) ? g_mulin : g_siglin;
    float x0 = x[c];
    float s = 0.f, q = 0.f;
    for (int b = threadIdx.x; b < B_; b += 256) {
        float d = x[b * K_ + c] - x0;
        s += d; q += d * d;
    }
    ssum[threadIdx.x] = s; ssq[threadIdx.x] = q;
    __syncthreads();
    for (int o = 128; o > 0; o >>= 1) {
        if (threadIdx.x < o) {
            ssum[threadIdx.x] += ssum[threadIdx.x + o];
            ssq[threadIdx.x]  += ssq[threadIdx.x + o];
        }
        __syncthreads();
    }
    if (threadIdx.x == 0) {
        float mean_d = ssum[0] * (1.f / B_);
        float var    = ssq[0] * (1.f / B_) - mean_d * mean_d;
        float mean   = x0 + mean_d;
        float g  = (col < K_) ? mug[c]  : sgg[c];
        float bbv = (col < K_) ? mubb[c] : sgbb[c];
        float a  = g * rsqrtf(var + BN_EPS);
        g_kA[col] = a;
        g_kC[col] = bbv - a * mean;
    }
}

__global__ void k_theta(const float* __restrict__ eps) {
    int i = blockIdx.x * blockDim.x + threadIdx.x;
    if (i >= B_ * K_) return;
    int k = i % K_;
    float m  = fmaf(g_kA[k], g_mulin[i], g_kC[k]);
    float sg = expf(0.5f * fmaf(g_kA[K_ + k], g_siglin[i], g_kC[K_ + k]));
    g_theta[i] = expf(fmaf(sg, eps[i], m));
}

__global__ void k_zero() {
    int i = blockIdx.x * blockDim.x + threadIdx.x;
    if (i < V_) g_cnt[i] = 0;
}
__global__ void k_hist(const int* __restrict__ tok) {
    int i = blockIdx.x * blockDim.x + threadIdx.x;
    if (i < T_) atomicAdd(&g_cnt[tok[i]], 1);
}

__global__ __launch_bounds__(256) void k_xstats(const float* __restrict__ bg,
                                                const float* __restrict__ bbb) {
    __shared__ float ss[8][32], sq[8][32];
    const int tx = threadIdx.x, ty = threadIdx.y;
    const int v  = blockIdx.x * 32 + tx;
    const bool ok = (v < V_);
    float s = 0.f, q = 0.f, x0 = 0.f;
    if (ok) {
        x0 = g_X[v];
        for (int b = ty; b < B_; b += 8) {
            float d = g_X[(size_t)b * V_ + v] - x0;
            s += d; q += d * d;
        }
    }
    ss[ty][tx] = s; sq[ty][tx] = q;
    __syncthreads();
    if (ty == 0 && ok) {
        float S = 0.f, Q = 0.f;
        for (int t = 0; t < 8; t++) { S += ss[t][tx]; Q += sq[t][tx]; }
        float mean_d = S * (1.f / B_);
        float var    = Q * (1.f / B_) - mean_d * mean_d;
        float mean   = x0 + mean_d;
        float a = bg[v] * rsqrtf(var + BN_EPS);
        g_av[v] = a;
        g_cv[v] = bbb[v] - a * mean;
    }
}

__global__ __launch_bounds__(512) void k_final() {
    __shared__ float sa[512], sc[512], scn[512];
    const int chunk = blockIdx.x;
    const int rg    = blockIdx.y;
    const int t     = threadIdx.x;
    const int v0    = chunk * 512;
    {
        int v = v0 + t;
        sa[t]  = (v < V_) ? g_av[v] : 0.f;
        sc[t]  = (v < V_) ? g_cv[v] : 0.f;
        scn[t] = (v < V_) ? (float)g_cnt[v] : 0.f;
    }
    __syncthreads();
    const int wrp  = t >> 5;
    const int lane = t & 31;
    const int b    = rg * 16 + wrp;
    const float* xr = g_X + (size_t)b * V_;
    float e = 0.f, wsum = 0.f;
#pragma unroll
    for (int j = 0; j < 16; j++) {
        int i = lane + j * 32;
        int v = v0 + i;
        if (v < V_) {
            float y = fmaf(sa[i], xr[v], sc[i]);
            e += exp_fast(y);
            wsum = fmaf(scn[i], y, wsum);
        }
    }
#pragma unroll
    for (int o = 16; o > 0; o >>= 1) {
        e    += __shfl_down_sync(0xffffffffu, e, o);
        wsum += __shfl_down_sync(0xffffffffu, wsum, o);
    }
    if (lane == 0) {
        g_ep[b * NC + chunk] = e;
        g_wp[b * NC + chunk] = wsum;
    }
}

__global__ void k_finish(float* __restrict__ out) {
    int b = blockIdx.x * blockDim.x + threadIdx.x;
    if (b >= B_) return;
    float E = 0.f, W = 0.f;
    for (int c = 0; c < NC; c++) { E += g_ep[b * NC + c]; W += g_wp[b * NC + c]; }
    out[b] = W - (float)T_ * logf(E);
}

extern "C" void kernel_launch(void* const* d_in, const int* in_sizes, int n_in,
                              void* d_out, int out_size) {
    const float* bows = (const float*)d_in[0];
    const float* eps  = (const float*)d_in[1];
    const int*   tok  = (const int*)  d_in[2];
    const float* fc1w = (const float*)d_in[3];
    const float* fc1b = (const float*)d_in[4];
    const float* fc2w = (const float*)d_in[5];
    const float* fc2b = (const float*)d_in[6];
    const float* muw  = (const float*)d_in[7];
    const float* mub  = (const float*)d_in[8];
    const float* bnmg = (const float*)d_in[9];
    const float* bnmb = (const float*)d_in[10];
    const float* sgw  = (const float*)d_in[11];
    const float* sgb  = (const float*)d_in[12];
    const float* bnsg = (const float*)d_in[13];
    const float* bnsb = (const float*)d_in[14];
    const float* btw  = (const float*)d_in[15];
    const float* btb  = (const float*)d_in[16];
    const float* bnbg = (const float*)d_in[17];
    const float* bnbb = (const float*)d_in[18];
    float* out = (float*)d_out;

    // 64KB dynamic smem opt-in (host-side attr; idempotent; capture-safe)
    cudaFuncSetAttribute(k_gemm1m, cudaFuncAttributeMaxDynamicSharedMemorySize, 65536);
    cudaFuncSetAttribute(k_gemm2m, cudaFuncAttributeMaxDynamicSharedMemorySize, 65536);

    // order: ncu capture slot (4th launch) = k_gemm1m
    k_prepA1<<<(int)(((size_t)B_ * V_ + 255) / 256), 256>>>(bows);
    k_prepB1<<<(int)(((size_t)V_ * 128 + 255) / 256), 256>>>(fc1w);
    k_pad1  <<<(B_ * (K1P - 3 * V_) + (K1P - 3 * V_) * 128 + 255) / 256, 256>>>();
    k_gemm1m<<<dim3(S1, B_ / 128), 256, 65536>>>();
    k_zero  <<<(V_ + 255) / 256, 256>>>();
    k_hist  <<<(T_ + 255) / 256, 256>>>(tok);
    k_red1  <<<(B_ * H_ + 255) / 256, 256>>>(fc1b);
    k_h2    <<<(B_ * H_ + 255) / 256, 256>>>(fc2w, fc2b);
    k_musig <<<(2 * B_ * K_ + 255) / 256, 256>>>(muw, mub, sgw, sgb);
    k_bnk   <<<2 * K_, 256>>>(bnmg, bnmb, bnsg, bnsb);
    k_theta <<<(B_ * K_ + 255) / 256, 256>>>(eps);
    k_prepA2<<<(B_ * K2PAD + 255) / 256, 256>>>();
    k_prepB2<<<(int)(((size_t)K2PAD * V_ + 255) / 256), 256>>>(btw);
    k_gemm2m<<<dim3((V_ + 127) / 128, B_ / 128), 256, 65536>>>(btb);
    k_xstats<<<(V_ + 31) / 32, dim3(32, 8)>>>(bnbg, bnbb);
    k_final <<<dim3(NC, B_ / 16), 512>>>();
    k_finish<<<(B_ + 255) / 256, 256>>>(out);
}